// round 1
// baseline (speedup 1.0000x reference)
#include <cuda_runtime.h>
#include <math.h>

#define DIM   192
#define HEADS 6
#define HD    32
#define RLOW  128
#define NSEQ  3136
#define BATCH 32
#define MTOT  (BATCH * NSEQ)   // 100352

// ---- scratch (device globals; no allocations allowed) ----
__device__ float g_q[MTOT * DIM];           // (b, head, n, hd) layout, pre-scaled
__device__ float g_k[MTOT * DIM];           // (b, n, c) layout
__device__ float g_v[MTOT * DIM];           // (b, n, c) layout
__device__ float g_klow[BATCH * RLOW * DIM];
__device__ float g_vlow[BATCH * RLOW * DIM];
__device__ float g_att[MTOT * DIM];         // (b, n, c) attention output pre-proj

// ============================================================
// Kernel A: fused window_reverse + QKV GEMM
//   out[m, j] = sum_k xm[m, k] * qkv_w[j, k] + qkv_b[j]
//   M = 100352, N = 576, K = 192. Tile 64x64, Kt = 16.
//   Scatters to g_q (scaled), g_k, g_v.
// ============================================================
__global__ __launch_bounds__(256) void qkv_kernel(const float* __restrict__ x,
                                                  const float* __restrict__ W,
                                                  const float* __restrict__ bias)
{
    __shared__ float As[16][65];
    __shared__ float Bs[16][65];
    __shared__ int   rowoff[64];

    const int t  = threadIdx.x;
    const int m0 = blockIdx.x * 64;
    const int j0 = blockIdx.y * 64;

    if (t < 64) {
        int m   = m0 + t;
        int bb  = m / NSEQ, n = m - bb * NSEQ;
        int r56 = n / 56, c56 = n - r56 * 56;
        int hb  = r56 / 7, hi = r56 - hb * 7;
        int wb  = c56 / 7, wi = c56 - wb * 7;
        rowoff[t] = ((bb * 64 + hb * 8 + wb) * 49 + hi * 7 + wi) * DIM;
    }

    float acc[4][4] = {};
    const int tx = t & 15, ty = t >> 4;

    for (int k0 = 0; k0 < DIM; k0 += 16) {
        __syncthreads();
#pragma unroll
        for (int l = 0; l < 4; l++) {
            int idx = t + 256 * l;
            int row = idx >> 4, kk = idx & 15;
            As[kk][row] = x[rowoff[row] + k0 + kk];
            Bs[kk][row] = W[(j0 + row) * DIM + k0 + kk];
        }
        __syncthreads();
#pragma unroll
        for (int kk = 0; kk < 16; kk++) {
            float a[4], bfr[4];
#pragma unroll
            for (int i = 0; i < 4; i++) a[i] = As[kk][ty * 4 + i];
#pragma unroll
            for (int j = 0; j < 4; j++) bfr[j] = Bs[kk][tx * 4 + j];
#pragma unroll
            for (int i = 0; i < 4; i++)
#pragma unroll
                for (int j = 0; j < 4; j++) acc[i][j] += a[i] * bfr[j];
        }
    }

    const float scale = 0.17677669529663687f; // 1/sqrt(32)
#pragma unroll
    for (int i = 0; i < 4; i++) {
        int m  = m0 + ty * 4 + i;
        int bb = m / NSEQ, n = m - bb * NSEQ;
#pragma unroll
        for (int j = 0; j < 4; j++) {
            int col = j0 + tx * 4 + j;
            float v = acc[i][j] + bias[col];
            if (col < DIM) {
                int hh = col >> 5, d = col & 31;
                g_q[((bb * HEADS + hh) * NSEQ + n) * HD + d] = v * scale;
            } else if (col < 2 * DIM) {
                g_k[m * DIM + (col - DIM)] = v;
            } else {
                g_v[m * DIM + (col - 2 * DIM)] = v;
            }
        }
    }
}

// ============================================================
// Kernel B: low-rank projection (heads fused into C=192)
//   klow[b, r, c] = sum_n E_w[r, n] * g_k[b, n, c] + E_b[r]   (and F/v)
//   Per block: 128 x 64 tile of one (b, which). K = 3136, Kt = 16.
// ============================================================
__global__ __launch_bounds__(256) void lowrank_kernel(const float* __restrict__ E,
                                                      const float* __restrict__ Ebias,
                                                      const float* __restrict__ F,
                                                      const float* __restrict__ Fbias)
{
    __shared__ float As[16][129];
    __shared__ float Bs[16][65];

    const int t     = threadIdx.x;
    const int c0    = blockIdx.x * 64;
    const int b     = blockIdx.y;
    const int which = blockIdx.z;

    const float* A    = which ? F : E;
    const float* bias = which ? Fbias : Ebias;
    const float* Bm   = which ? g_v : g_k;
    float*       out  = which ? g_vlow : g_klow;

    const float* Bbase = Bm + b * NSEQ * DIM + c0;

    float acc[8][4] = {};
    const int tx = t & 15, ty = t >> 4;

    for (int k0 = 0; k0 < NSEQ; k0 += 16) {
        __syncthreads();
#pragma unroll
        for (int l = 0; l < 8; l++) {
            int idx = t + 256 * l;
            int r = idx >> 4, kk = idx & 15;
            As[kk][r] = A[r * NSEQ + k0 + kk];
        }
#pragma unroll
        for (int l = 0; l < 4; l++) {
            int idx = t + 256 * l;
            int kk = idx >> 6, jj = idx & 63;
            Bs[kk][jj] = Bbase[(k0 + kk) * DIM + jj];
        }
        __syncthreads();
#pragma unroll
        for (int kk = 0; kk < 16; kk++) {
            float a[8], bfr[4];
#pragma unroll
            for (int i = 0; i < 8; i++) a[i] = As[kk][ty * 8 + i];
#pragma unroll
            for (int j = 0; j < 4; j++) bfr[j] = Bs[kk][tx * 4 + j];
#pragma unroll
            for (int i = 0; i < 8; i++)
#pragma unroll
                for (int j = 0; j < 4; j++) acc[i][j] += a[i] * bfr[j];
        }
    }

#pragma unroll
    for (int i = 0; i < 8; i++) {
        int r    = ty * 8 + i;
        float bv = bias[r];
#pragma unroll
        for (int j = 0; j < 4; j++) {
            int col = c0 + tx * 4 + j;
            out[(b * RLOW + r) * DIM + col] = acc[i][j] + bv;
        }
    }
}

// ============================================================
// Kernel C: fused attention per (b, head, 64 n-rows)
//   attn = q @ klow^T (64x128), softmax over 128, out = attn @ vlow (64x32)
//   All intermediates in SMEM; attn never hits HBM.
// ============================================================
#define AT_STRIDE 132
__global__ __launch_bounds__(256) void attn_kernel()
{
    extern __shared__ float sm[];
    float* klow_s = sm;                              // 128 x 33
    float* vlow_s = sm + 128 * 33;                   // 128 x 33
    float* q_s    = sm + 2 * 128 * 33;               // 64 x 33
    float* attn_s = sm + 2 * 128 * 33 + 64 * 33;     // 64 x 132
    float* rowsum = attn_s + 64 * AT_STRIDE;         // 64

    const int t  = threadIdx.x;
    const int n0 = blockIdx.x * 64;
    const int hh = blockIdx.y;
    const int b  = blockIdx.z;

    const float* kl = g_klow + b * RLOW * DIM + hh * HD;
    const float* vl = g_vlow + b * RLOW * DIM + hh * HD;
#pragma unroll
    for (int l = 0; l < 16; l++) {
        int idx = t + 256 * l;
        int r = idx >> 5, d = idx & 31;
        klow_s[r * 33 + d] = kl[r * DIM + d];
        vlow_s[r * 33 + d] = vl[r * DIM + d];
    }
    const float* qp = g_q + ((b * HEADS + hh) * NSEQ + n0) * HD;
#pragma unroll
    for (int l = 0; l < 8; l++) {
        int idx = t + 256 * l;
        int i = idx >> 5, d = idx & 31;
        q_s[i * 33 + d] = qp[i * HD + d];
    }
    __syncthreads();

    // Phase 1: attn[i][r] = sum_d q[i][d] * klow[r][d]  (64x128, K=32)
    {
        const int tx = t & 31, ty = t >> 5;   // ty<8 -> 8 i-rows each, r = tx + 32*j
        float acc[8][4] = {};
#pragma unroll
        for (int d = 0; d < 32; d++) {
            float a[8], kb[4];
#pragma unroll
            for (int i = 0; i < 8; i++) a[i] = q_s[(ty * 8 + i) * 33 + d];
#pragma unroll
            for (int j = 0; j < 4; j++) kb[j] = klow_s[(tx + 32 * j) * 33 + d];
#pragma unroll
            for (int i = 0; i < 8; i++)
#pragma unroll
                for (int j = 0; j < 4; j++) acc[i][j] += a[i] * kb[j];
        }
#pragma unroll
        for (int i = 0; i < 8; i++)
#pragma unroll
            for (int j = 0; j < 4; j++)
                attn_s[(ty * 8 + i) * AT_STRIDE + tx + 32 * j] = acc[i][j];
    }
    __syncthreads();

    // Phase 2: softmax (stores exp values; normalization folded into phase 3)
    {
        int row = t >> 2, part = t & 3;
        float* ap = attn_s + row * AT_STRIDE + part * 32;
        float mx = -1e30f;
#pragma unroll
        for (int j = 0; j < 32; j++) mx = fmaxf(mx, ap[j]);
        mx = fmaxf(mx, __shfl_xor_sync(0xffffffff, mx, 1));
        mx = fmaxf(mx, __shfl_xor_sync(0xffffffff, mx, 2));
        float s = 0.f;
#pragma unroll
        for (int j = 0; j < 32; j++) { float e = __expf(ap[j] - mx); ap[j] = e; s += e; }
        s += __shfl_xor_sync(0xffffffff, s, 1);
        s += __shfl_xor_sync(0xffffffff, s, 2);
        if (part == 0) rowsum[row] = s;
    }
    __syncthreads();

    // Phase 3: out[i][d] = (sum_r attn[i][r] * vlow[r][d]) / rowsum[i]
    {
        const int dx = t & 7, ty = t >> 3;   // 4 d-cols, 2 i-rows per thread
        float acc[2][4] = {};
        for (int r = 0; r < 128; r++) {
            float a0 = attn_s[(ty * 2 + 0) * AT_STRIDE + r];
            float a1 = attn_s[(ty * 2 + 1) * AT_STRIDE + r];
#pragma unroll
            for (int j = 0; j < 4; j++) {
                float vv = vlow_s[r * 33 + dx * 4 + j];
                acc[0][j] += a0 * vv;
                acc[1][j] += a1 * vv;
            }
        }
#pragma unroll
        for (int c = 0; c < 2; c++) {
            int i = ty * 2 + c;
            float inv = 1.0f / rowsum[i];
            float* op = g_att + (b * NSEQ + n0 + i) * DIM + hh * HD + dx * 4;
#pragma unroll
            for (int j = 0; j < 4; j++) op[j] = acc[c][j] * inv;
        }
    }
}

// ============================================================
// Kernel D: output projection
//   out[m, j] = sum_c g_att[m, c] * proj_w[j, c] + proj_b[j]
// ============================================================
__global__ __launch_bounds__(256) void proj_kernel(const float* __restrict__ W,
                                                   const float* __restrict__ bias,
                                                   float* __restrict__ out)
{
    __shared__ float As[16][65];
    __shared__ float Bs[16][65];

    const int t  = threadIdx.x;
    const int m0 = blockIdx.x * 64;
    const int j0 = blockIdx.y * 64;

    float acc[4][4] = {};
    const int tx = t & 15, ty = t >> 4;

    for (int k0 = 0; k0 < DIM; k0 += 16) {
        __syncthreads();
#pragma unroll
        for (int l = 0; l < 4; l++) {
            int idx = t + 256 * l;
            int row = idx >> 4, kk = idx & 15;
            As[kk][row] = g_att[(m0 + row) * DIM + k0 + kk];
            Bs[kk][row] = W[(j0 + row) * DIM + k0 + kk];
        }
        __syncthreads();
#pragma unroll
        for (int kk = 0; kk < 16; kk++) {
            float a[4], bfr[4];
#pragma unroll
            for (int i = 0; i < 4; i++) a[i] = As[kk][ty * 4 + i];
#pragma unroll
            for (int j = 0; j < 4; j++) bfr[j] = Bs[kk][tx * 4 + j];
#pragma unroll
            for (int i = 0; i < 4; i++)
#pragma unroll
                for (int j = 0; j < 4; j++) acc[i][j] += a[i] * bfr[j];
        }
    }

#pragma unroll
    for (int i = 0; i < 4; i++) {
        int m = m0 + ty * 4 + i;
#pragma unroll
        for (int j = 0; j < 4; j++) {
            int col = j0 + tx * 4 + j;
            out[m * DIM + col] = acc[i][j] + bias[col];
        }
    }
}

// ============================================================
extern "C" void kernel_launch(void* const* d_in, const int* in_sizes, int n_in,
                              void* d_out, int out_size)
{
    const float* x      = (const float*)d_in[0];
    const float* qkv_w  = (const float*)d_in[1];
    const float* qkv_b  = (const float*)d_in[2];
    const float* E_w    = (const float*)d_in[3];
    const float* E_b    = (const float*)d_in[4];
    const float* F_w    = (const float*)d_in[5];
    const float* F_b    = (const float*)d_in[6];
    const float* proj_w = (const float*)d_in[7];
    const float* proj_b = (const float*)d_in[8];
    float* out = (float*)d_out;

    const size_t smem = (size_t)(2 * 128 * 33 + 64 * 33 + 64 * AT_STRIDE + 64) * sizeof(float);
    cudaFuncSetAttribute(attn_kernel, cudaFuncAttributeMaxDynamicSharedMemorySize, (int)smem);

    qkv_kernel<<<dim3(MTOT / 64, 9), 256>>>(x, qkv_w, qkv_b);
    lowrank_kernel<<<dim3(3, BATCH, 2), 256>>>(E_w, E_b, F_w, F_b);
    attn_kernel<<<dim3(NSEQ / 64, HEADS, BATCH), 256, smem>>>();
    proj_kernel<<<dim3(MTOT / 64, 3), 256>>>(proj_w, proj_b, out);
}

// round 3
// speedup vs baseline: 2.1333x; 2.1333x over previous
#include <cuda_runtime.h>
#include <cuda_bf16.h>
#include <cstdint>
#include <math.h>

#define DIM   192
#define HEADS 6
#define HD    32
#define RLOW  128
#define NSEQ  3136
#define BATCH 32
#define MTOT  (BATCH * NSEQ)   // 100352

// ================= scratch (device globals) =================
__device__ __align__(256) float g_q[MTOT * DIM];                    // (b,h,n,d) fp32, pre-scaled
__device__ __align__(256) __nv_bfloat16 g_xh[MTOT * DIM], g_xl[MTOT * DIM];   // x split (window order)
__device__ __align__(256) __nv_bfloat16 g_kTh[MTOT * DIM], g_kTl[MTOT * DIM]; // K^T (b,c,n) split
__device__ __align__(256) __nv_bfloat16 g_vTh[MTOT * DIM], g_vTl[MTOT * DIM]; // V^T (b,c,n) split
__device__ __align__(256) __nv_bfloat16 g_ah[MTOT * DIM], g_al[MTOT * DIM];   // attn out (b,n,c) split
__device__ __align__(256) float g_klow[BATCH * RLOW * DIM];
__device__ __align__(256) float g_vlow[BATCH * RLOW * DIM];
__device__ __align__(256) __nv_bfloat16 g_wqh[3 * DIM * DIM], g_wql[3 * DIM * DIM];
__device__ __align__(256) __nv_bfloat16 g_wph[DIM * DIM], g_wpl[DIM * DIM];
__device__ __align__(256) __nv_bfloat16 g_Eh[RLOW * NSEQ], g_El[RLOW * NSEQ];
__device__ __align__(256) __nv_bfloat16 g_Fh[RLOW * NSEQ], g_Fl[RLOW * NSEQ];

// ================= helpers =================
__device__ __forceinline__ uint32_t smem_u32(const void* p) {
    uint32_t a;
    asm("{ .reg .u64 t; cvta.to.shared.u64 t, %1; cvt.u32.u64 %0, t; }" : "=r"(a) : "l"(p));
    return a;
}
__device__ __forceinline__ void ldsm4(uint32_t r[4], uint32_t a) {
    asm volatile("ldmatrix.sync.aligned.m8n8.x4.shared.b16 {%0,%1,%2,%3}, [%4];"
                 : "=r"(r[0]), "=r"(r[1]), "=r"(r[2]), "=r"(r[3]) : "r"(a));
}
__device__ __forceinline__ void mma16816(float* c, const uint32_t a[4], uint32_t b0, uint32_t b1) {
    asm volatile("mma.sync.aligned.m16n8k16.row.col.f32.bf16.bf16.f32 "
                 "{%0,%1,%2,%3},{%4,%5,%6,%7},{%8,%9},{%0,%1,%2,%3};"
                 : "+f"(c[0]), "+f"(c[1]), "+f"(c[2]), "+f"(c[3])
                 : "r"(a[0]), "r"(a[1]), "r"(a[2]), "r"(a[3]), "r"(b0), "r"(b1));
}
__device__ __forceinline__ void cpa16(uint32_t saddr, const void* g) {
    asm volatile("cp.async.ca.shared.global [%0], [%1], 16;" :: "r"(saddr), "l"(g));
}
#define CPA_COMMIT() asm volatile("cp.async.commit_group;" ::: "memory")
#define CPA_WAIT1()  asm volatile("cp.async.wait_group 1;" ::: "memory")
#define CPA_WAIT0()  asm volatile("cp.async.wait_group 0;" ::: "memory")

__device__ __forceinline__ void split_bf16(float v, __nv_bfloat16& h, __nv_bfloat16& l) {
    h = __float2bfloat16(v);
    l = __float2bfloat16(v - __bfloat162float(h));
}

// ================= smem layout for GEMM kernels =================
// stage: A_hi 128x64 (144B rows) | A_lo | B_hi 64x64 | B_lo  = 55296 B
#define ROWB  144
#define SA_L  18432
#define SB_H  36864
#define SB_L  46080
#define STG   55296
#define SOFF  512                      // rowoff area (qkv only)
#define SMEM_GEMM (SOFF + 2 * STG)     // 111104

// compute one K=64 chunk: 3-term split mma, warp tile 32x32 (4x2 warps)
__device__ __forceinline__ void compute_chunk(uint32_t st, int wm, int wn, int lane,
                                              float acc[2][4][4])
{
    uint32_t a0r = st + (wm * 32 + (lane & 15)) * ROWB + ((lane >> 4) & 1) * 16;
    uint32_t b0r = st + SB_H + (wn * 32 + (lane & 7) + ((lane >> 4) & 1) * 8) * ROWB
                   + ((lane >> 3) & 1) * 16;
#pragma unroll
    for (int ks = 0; ks < 4; ks++) {
        uint32_t ah[2][4], al[2][4], bhA[4], bhB[4], blA[4], blB[4];
        ldsm4(ah[0], a0r + ks * 32);
        ldsm4(ah[1], a0r + 16 * ROWB + ks * 32);
        ldsm4(al[0], a0r + SA_L + ks * 32);
        ldsm4(al[1], a0r + SA_L + 16 * ROWB + ks * 32);
        ldsm4(bhA, b0r + ks * 32);
        ldsm4(bhB, b0r + 16 * ROWB + ks * 32);
        ldsm4(blA, b0r + (SB_L - SB_H) + ks * 32);
        ldsm4(blB, b0r + (SB_L - SB_H) + 16 * ROWB + ks * 32);
        uint32_t bh[4][2] = {{bhA[0], bhA[1]}, {bhA[2], bhA[3]}, {bhB[0], bhB[1]}, {bhB[2], bhB[3]}};
        uint32_t bl[4][2] = {{blA[0], blA[1]}, {blA[2], blA[3]}, {blB[0], blB[1]}, {blB[2], blB[3]}};
#pragma unroll
        for (int mf = 0; mf < 2; mf++)
#pragma unroll
            for (int nf = 0; nf < 4; nf++) {
                mma16816(acc[mf][nf], ah[mf], bh[nf][0], bh[nf][1]);
                mma16816(acc[mf][nf], al[mf], bh[nf][0], bh[nf][1]);
                mma16816(acc[mf][nf], ah[mf], bl[nf][0], bl[nf][1]);
            }
    }
}

// ================= split conversion kernel =================
__global__ void split_kernel(const float* __restrict__ in, __nv_bfloat16* __restrict__ hi,
                             __nv_bfloat16* __restrict__ lo, int n4)
{
    int i = blockIdx.x * blockDim.x + threadIdx.x;
    if (i >= n4) return;
    float4 v = reinterpret_cast<const float4*>(in)[i];
    __nv_bfloat162 h01 = __floats2bfloat162_rn(v.x, v.y);
    __nv_bfloat162 h23 = __floats2bfloat162_rn(v.z, v.w);
    float2 f01 = __bfloat1622float2(h01), f23 = __bfloat1622float2(h23);
    __nv_bfloat162 l01 = __floats2bfloat162_rn(v.x - f01.x, v.y - f01.y);
    __nv_bfloat162 l23 = __floats2bfloat162_rn(v.z - f23.x, v.w - f23.y);
    reinterpret_cast<__nv_bfloat162*>(hi)[2 * i]     = h01;
    reinterpret_cast<__nv_bfloat162*>(hi)[2 * i + 1] = h23;
    reinterpret_cast<__nv_bfloat162*>(lo)[2 * i]     = l01;
    reinterpret_cast<__nv_bfloat162*>(lo)[2 * i + 1] = l23;
}

// ================= QKV: M=128 N=64 K=192 per CTA =================
__global__ __launch_bounds__(256) void qkv_mma(const float* __restrict__ bias)
{
    extern __shared__ char sm[];
    uint32_t sb = smem_u32(sm);
    const int t = threadIdx.x, lane = t & 31, wid = t >> 5;
    const int wm = wid & 3, wn = wid >> 2;
    const int m0 = blockIdx.x * 128, j0 = blockIdx.y * 64;
    int* rowoff = (int*)sm;

    if (t < 128) {
        int m   = m0 + t;
        int bb  = m / NSEQ, n = m - bb * NSEQ;
        int r56 = n / 56, c56 = n - r56 * 56;
        int hb  = r56 / 7, hi_ = r56 - hb * 7;
        int wb  = c56 / 7, wi = c56 - wb * 7;
        rowoff[t] = ((bb * 64 + hb * 8 + wb) * 49 + hi_ * 7 + wi) * DIM;
    }
    __syncthreads();

    auto issue = [&](int i) {
        uint32_t st = sb + SOFF + (i & 1) * STG;
        int k0 = i * 64;
#pragma unroll
        for (int l = 0; l < 4; l++) {
            int idx = t + 256 * l;
            int row = idx >> 3, cg = idx & 7;
            uint32_t so = row * ROWB + cg * 16;
            int gi = rowoff[row] + k0 + cg * 8;
            cpa16(st + so, g_xh + gi);
            cpa16(st + SA_L + so, g_xl + gi);
        }
#pragma unroll
        for (int l = 0; l < 2; l++) {
            int idx = t + 256 * l;
            int row = idx >> 3, cg = idx & 7;
            uint32_t so = row * ROWB + cg * 16;
            int gi = (j0 + row) * DIM + k0 + cg * 8;
            cpa16(st + SB_H + so, g_wqh + gi);
            cpa16(st + SB_L + so, g_wql + gi);
        }
        CPA_COMMIT();
    };

    float acc[2][4][4] = {};
    issue(0);
    for (int i = 0; i < 3; i++) {
        if (i < 2) { issue(i + 1); CPA_WAIT1(); } else { CPA_WAIT0(); }
        __syncthreads();
        compute_chunk(sb + SOFF + (i & 1) * STG, wm, wn, lane, acc);
        __syncthreads();
    }

    const int seg = j0 / DIM;          // 0=q 1=k 2=v
    const int jb  = j0 - seg * DIM;
    __nv_bfloat16* H = (seg == 1) ? g_kTh : g_vTh;
    __nv_bfloat16* L = (seg == 1) ? g_kTl : g_vTl;
    const float scale = 0.17677669529663687f;
#pragma unroll
    for (int mf = 0; mf < 2; mf++)
#pragma unroll
        for (int rr = 0; rr < 2; rr++) {
            int ml = wm * 32 + mf * 16 + (lane >> 2) + rr * 8;
            int m  = m0 + ml;
            int b  = m / NSEQ, n = m - b * NSEQ;
#pragma unroll
            for (int nf = 0; nf < 4; nf++)
#pragma unroll
                for (int cp = 0; cp < 2; cp++) {
                    int c = wn * 32 + nf * 8 + (lane & 3) * 2 + cp;
                    float v = acc[mf][nf][rr * 2 + cp] + bias[j0 + c];
                    if (seg == 0) {
                        int jj = jb + c;
                        g_q[((b * HEADS + (jj >> 5)) * NSEQ + n) * HD + (jj & 31)] = v * scale;
                    } else {
                        __nv_bfloat16 h_, l_;
                        split_bf16(v, h_, l_);
                        int idx = (b * DIM + jb + c) * NSEQ + n;
                        H[idx] = h_;
                        L[idx] = l_;
                    }
                }
        }
}

// ================= low-rank: M=128(R) N=64 K=3136 =================
__global__ __launch_bounds__(256) void lowrank_mma(const float* __restrict__ Eb,
                                                   const float* __restrict__ Fb)
{
    extern __shared__ char sm[];
    uint32_t sb = smem_u32(sm);
    const int t = threadIdx.x, lane = t & 31, wid = t >> 5;
    const int wm = wid & 3, wn = wid >> 2;
    const int c0 = blockIdx.x * 64, b = blockIdx.y, which = blockIdx.z;

    const __nv_bfloat16* Ah = which ? g_Fh : g_Eh;
    const __nv_bfloat16* Al = which ? g_Fl : g_El;
    const __nv_bfloat16* Bh = which ? g_vTh : g_kTh;
    const __nv_bfloat16* Bl = which ? g_vTl : g_kTl;
    const float* bias = which ? Fb : Eb;
    float* out = which ? g_vlow : g_klow;

    auto issue = [&](int i) {
        uint32_t st = sb + SOFF + (i & 1) * STG;
        int k0 = i * 64;
#pragma unroll
        for (int l = 0; l < 4; l++) {
            int idx = t + 256 * l;
            int row = idx >> 3, cg = idx & 7;
            uint32_t so = row * ROWB + cg * 16;
            int gi = row * NSEQ + k0 + cg * 8;
            cpa16(st + so, Ah + gi);
            cpa16(st + SA_L + so, Al + gi);
        }
#pragma unroll
        for (int l = 0; l < 2; l++) {
            int idx = t + 256 * l;
            int row = idx >> 3, cg = idx & 7;
            uint32_t so = row * ROWB + cg * 16;
            int gi = (b * DIM + c0 + row) * NSEQ + k0 + cg * 8;
            cpa16(st + SB_H + so, Bh + gi);
            cpa16(st + SB_L + so, Bl + gi);
        }
        CPA_COMMIT();
    };

    float acc[2][4][4] = {};
    issue(0);
    for (int i = 0; i < 49; i++) {
        if (i < 48) { issue(i + 1); CPA_WAIT1(); } else { CPA_WAIT0(); }
        __syncthreads();
        compute_chunk(sb + SOFF + (i & 1) * STG, wm, wn, lane, acc);
        __syncthreads();
    }

#pragma unroll
    for (int mf = 0; mf < 2; mf++)
#pragma unroll
        for (int rr = 0; rr < 2; rr++) {
            int r = wm * 32 + mf * 16 + (lane >> 2) + rr * 8;
            float bv = bias[r];
#pragma unroll
            for (int nf = 0; nf < 4; nf++)
#pragma unroll
                for (int cp = 0; cp < 2; cp++) {
                    int c = wn * 32 + nf * 8 + (lane & 3) * 2 + cp;
                    out[(b * RLOW + r) * DIM + c0 + c] = acc[mf][nf][rr * 2 + cp] + bv;
                }
        }
}

// ================= attention (SIMT fp32, writes split bf16) =================
#define AT_STRIDE 132
#define ATT_SMEM ((2 * 128 * 33 + 64 * 33 + 64 * AT_STRIDE + 64) * 4)
__global__ __launch_bounds__(256) void attn_kernel()
{
    extern __shared__ float smf[];
    float* klow_s = smf;
    float* vlow_s = smf + 128 * 33;
    float* q_s    = smf + 2 * 128 * 33;
    float* attn_s = smf + 2 * 128 * 33 + 64 * 33;
    float* rowsum = attn_s + 64 * AT_STRIDE;

    const int t  = threadIdx.x;
    const int n0 = blockIdx.x * 64;
    const int hh = blockIdx.y;
    const int b  = blockIdx.z;

    const float* kl = g_klow + b * RLOW * DIM + hh * HD;
    const float* vl = g_vlow + b * RLOW * DIM + hh * HD;
#pragma unroll
    for (int l = 0; l < 16; l++) {
        int idx = t + 256 * l;
        int r = idx >> 5, d = idx & 31;
        klow_s[r * 33 + d] = kl[r * DIM + d];
        vlow_s[r * 33 + d] = vl[r * DIM + d];
    }
    const float* qp = g_q + ((b * HEADS + hh) * NSEQ + n0) * HD;
#pragma unroll
    for (int l = 0; l < 8; l++) {
        int idx = t + 256 * l;
        int i = idx >> 5, d = idx & 31;
        q_s[i * 33 + d] = qp[i * HD + d];
    }
    __syncthreads();

    {
        const int tx = t & 31, ty = t >> 5;
        float acc[8][4] = {};
#pragma unroll
        for (int d = 0; d < 32; d++) {
            float a[8], kb[4];
#pragma unroll
            for (int i = 0; i < 8; i++) a[i] = q_s[(ty * 8 + i) * 33 + d];
#pragma unroll
            for (int j = 0; j < 4; j++) kb[j] = klow_s[(tx + 32 * j) * 33 + d];
#pragma unroll
            for (int i = 0; i < 8; i++)
#pragma unroll
                for (int j = 0; j < 4; j++) acc[i][j] += a[i] * kb[j];
        }
#pragma unroll
        for (int i = 0; i < 8; i++)
#pragma unroll
            for (int j = 0; j < 4; j++)
                attn_s[(ty * 8 + i) * AT_STRIDE + tx + 32 * j] = acc[i][j];
    }
    __syncthreads();

    {
        int row = t >> 2, part = t & 3;
        float* ap = attn_s + row * AT_STRIDE + part * 32;
        float mx = -1e30f;
#pragma unroll
        for (int j = 0; j < 32; j++) mx = fmaxf(mx, ap[j]);
        mx = fmaxf(mx, __shfl_xor_sync(0xffffffff, mx, 1));
        mx = fmaxf(mx, __shfl_xor_sync(0xffffffff, mx, 2));
        float s = 0.f;
#pragma unroll
        for (int j = 0; j < 32; j++) { float e = __expf(ap[j] - mx); ap[j] = e; s += e; }
        s += __shfl_xor_sync(0xffffffff, s, 1);
        s += __shfl_xor_sync(0xffffffff, s, 2);
        if (part == 0) rowsum[row] = s;
    }
    __syncthreads();

    {
        const int dx = t & 7, ty = t >> 3;
        float acc[2][4] = {};
        for (int r = 0; r < 128; r++) {
            float a0 = attn_s[(ty * 2 + 0) * AT_STRIDE + r];
            float a1 = attn_s[(ty * 2 + 1) * AT_STRIDE + r];
#pragma unroll
            for (int j = 0; j < 4; j++) {
                float vv = vlow_s[r * 33 + dx * 4 + j];
                acc[0][j] += a0 * vv;
                acc[1][j] += a1 * vv;
            }
        }
#pragma unroll
        for (int c = 0; c < 2; c++) {
            int i = ty * 2 + c;
            float inv = 1.0f / rowsum[i];
            int base = (b * NSEQ + n0 + i) * DIM + hh * HD + dx * 4;
#pragma unroll
            for (int j = 0; j < 4; j++) {
                float v = acc[c][j] * inv;
                __nv_bfloat16 h_, l_;
                split_bf16(v, h_, l_);
                g_ah[base + j] = h_;
                g_al[base + j] = l_;
            }
        }
    }
}

// ================= proj: M=128 N=64 K=192 per CTA =================
__global__ __launch_bounds__(256) void proj_mma(const float* __restrict__ bias,
                                                float* __restrict__ out)
{
    extern __shared__ char sm[];
    uint32_t sb = smem_u32(sm);
    const int t = threadIdx.x, lane = t & 31, wid = t >> 5;
    const int wm = wid & 3, wn = wid >> 2;
    const int m0 = blockIdx.x * 128, j0 = blockIdx.y * 64;

    auto issue = [&](int i) {
        uint32_t st = sb + SOFF + (i & 1) * STG;
        int k0 = i * 64;
#pragma unroll
        for (int l = 0; l < 4; l++) {
            int idx = t + 256 * l;
            int row = idx >> 3, cg = idx & 7;
            uint32_t so = row * ROWB + cg * 16;
            int gi = (m0 + row) * DIM + k0 + cg * 8;
            cpa16(st + so, g_ah + gi);
            cpa16(st + SA_L + so, g_al + gi);
        }
#pragma unroll
        for (int l = 0; l < 2; l++) {
            int idx = t + 256 * l;
            int row = idx >> 3, cg = idx & 7;
            uint32_t so = row * ROWB + cg * 16;
            int gi = (j0 + row) * DIM + k0 + cg * 8;
            cpa16(st + SB_H + so, g_wph + gi);
            cpa16(st + SB_L + so, g_wpl + gi);
        }
        CPA_COMMIT();
    };

    float acc[2][4][4] = {};
    issue(0);
    for (int i = 0; i < 3; i++) {
        if (i < 2) { issue(i + 1); CPA_WAIT1(); } else { CPA_WAIT0(); }
        __syncthreads();
        compute_chunk(sb + SOFF + (i & 1) * STG, wm, wn, lane, acc);
        __syncthreads();
    }

#pragma unroll
    for (int mf = 0; mf < 2; mf++)
#pragma unroll
        for (int rr = 0; rr < 2; rr++) {
            int m = m0 + wm * 32 + mf * 16 + (lane >> 2) + rr * 8;
#pragma unroll
            for (int nf = 0; nf < 4; nf++)
#pragma unroll
                for (int cp = 0; cp < 2; cp++) {
                    int c = wn * 32 + nf * 8 + (lane & 3) * 2 + cp;
                    out[m * DIM + j0 + c] = acc[mf][nf][rr * 2 + cp] + bias[j0 + c];
                }
        }
}

// ================= host =================
extern "C" void kernel_launch(void* const* d_in, const int* in_sizes, int n_in,
                              void* d_out, int out_size)
{
    const float* x      = (const float*)d_in[0];
    const float* qkv_w  = (const float*)d_in[1];
    const float* qkv_b  = (const float*)d_in[2];
    const float* E_w    = (const float*)d_in[3];
    const float* E_b    = (const float*)d_in[4];
    const float* F_w    = (const float*)d_in[5];
    const float* F_b    = (const float*)d_in[6];
    const float* proj_w = (const float*)d_in[7];
    const float* proj_b = (const float*)d_in[8];
    float* out = (float*)d_out;

    cudaFuncSetAttribute(qkv_mma, cudaFuncAttributeMaxDynamicSharedMemorySize, SMEM_GEMM);
    cudaFuncSetAttribute(lowrank_mma, cudaFuncAttributeMaxDynamicSharedMemorySize, SMEM_GEMM);
    cudaFuncSetAttribute(proj_mma, cudaFuncAttributeMaxDynamicSharedMemorySize, SMEM_GEMM);
    cudaFuncSetAttribute(attn_kernel, cudaFuncAttributeMaxDynamicSharedMemorySize, ATT_SMEM);

    __nv_bfloat16 *xh, *xl, *wqh, *wql, *wph, *wpl, *Eh, *El, *Fh, *Fl;
    cudaGetSymbolAddress((void**)&xh, g_xh);   cudaGetSymbolAddress((void**)&xl, g_xl);
    cudaGetSymbolAddress((void**)&wqh, g_wqh); cudaGetSymbolAddress((void**)&wql, g_wql);
    cudaGetSymbolAddress((void**)&wph, g_wph); cudaGetSymbolAddress((void**)&wpl, g_wpl);
    cudaGetSymbolAddress((void**)&Eh, g_Eh);   cudaGetSymbolAddress((void**)&El, g_El);
    cudaGetSymbolAddress((void**)&Fh, g_Fh);   cudaGetSymbolAddress((void**)&Fl, g_Fl);

    int n4x = MTOT * DIM / 4;
    split_kernel<<<(n4x + 255) / 256, 256>>>(x, xh, xl, n4x);
    int n4q = 3 * DIM * DIM / 4;
    split_kernel<<<(n4q + 255) / 256, 256>>>(qkv_w, wqh, wql, n4q);
    int n4e = RLOW * NSEQ / 4;
    split_kernel<<<(n4e + 255) / 256, 256>>>(E_w, Eh, El, n4e);
    split_kernel<<<(n4e + 255) / 256, 256>>>(F_w, Fh, Fl, n4e);
    int n4p = DIM * DIM / 4;
    split_kernel<<<(n4p + 255) / 256, 256>>>(proj_w, wph, wpl, n4p);

    qkv_mma<<<dim3(MTOT / 128, 9), 256, SMEM_GEMM>>>(qkv_b);
    lowrank_mma<<<dim3(3, BATCH, 2), 256, SMEM_GEMM>>>(E_b, F_b);
    attn_kernel<<<dim3(NSEQ / 64, HEADS, BATCH), 256, ATT_SMEM>>>();
    proj_mma<<<dim3(MTOT / 128, 3), 256, SMEM_GEMM>>>(proj_b, out);
}

// round 4
// speedup vs baseline: 2.7666x; 1.2969x over previous
#include <cuda_runtime.h>
#include <cuda_bf16.h>
#include <cstdint>
#include <math.h>

#define DIM   192
#define HEADS 6
#define HD    32
#define RLOW  128
#define NSEQ  3136
#define BATCH 32
#define MTOT  (BATCH * NSEQ)   // 100352

// ================= scratch (device globals) =================
__device__ __align__(256) __nv_bfloat16 g_xh[MTOT * DIM], g_xl[MTOT * DIM];   // x split (window order)
__device__ __align__(256) __nv_bfloat16 g_qh[MTOT * DIM], g_ql[MTOT * DIM];   // q (b,h,n,d) split, pre-scaled
__device__ __align__(256) __nv_bfloat16 g_kTh[MTOT * DIM], g_kTl[MTOT * DIM]; // K^T (b,c,n) split
__device__ __align__(256) __nv_bfloat16 g_vTh[MTOT * DIM], g_vTl[MTOT * DIM]; // V^T (b,c,n) split
__device__ __align__(256) __nv_bfloat16 g_ah[MTOT * DIM], g_al[MTOT * DIM];   // attn out (b,n,c) split
__device__ __align__(256) __nv_bfloat16 g_klh[BATCH * RLOW * DIM], g_kll[BATCH * RLOW * DIM]; // klow (b,R,c)
__device__ __align__(256) __nv_bfloat16 g_vlh[BATCH * DIM * RLOW], g_vll[BATCH * DIM * RLOW]; // vlow^T (b,c,R)
__device__ __align__(256) __nv_bfloat16 g_wqh[3 * DIM * DIM], g_wql[3 * DIM * DIM];
__device__ __align__(256) __nv_bfloat16 g_wph[DIM * DIM], g_wpl[DIM * DIM];
__device__ __align__(256) __nv_bfloat16 g_Eh[RLOW * NSEQ], g_El[RLOW * NSEQ];
__device__ __align__(256) __nv_bfloat16 g_Fh[RLOW * NSEQ], g_Fl[RLOW * NSEQ];

// ================= helpers =================
__device__ __forceinline__ uint32_t smem_u32(const void* p) {
    uint32_t a;
    asm("{ .reg .u64 t; cvta.to.shared.u64 t, %1; cvt.u32.u64 %0, t; }" : "=r"(a) : "l"(p));
    return a;
}
__device__ __forceinline__ void ldsm4(uint32_t r[4], uint32_t a) {
    asm volatile("ldmatrix.sync.aligned.m8n8.x4.shared.b16 {%0,%1,%2,%3}, [%4];"
                 : "=r"(r[0]), "=r"(r[1]), "=r"(r[2]), "=r"(r[3]) : "r"(a));
}
__device__ __forceinline__ void mma16816(float* c, const uint32_t a[4], uint32_t b0, uint32_t b1) {
    asm volatile("mma.sync.aligned.m16n8k16.row.col.f32.bf16.bf16.f32 "
                 "{%0,%1,%2,%3},{%4,%5,%6,%7},{%8,%9},{%0,%1,%2,%3};"
                 : "+f"(c[0]), "+f"(c[1]), "+f"(c[2]), "+f"(c[3])
                 : "r"(a[0]), "r"(a[1]), "r"(a[2]), "r"(a[3]), "r"(b0), "r"(b1));
}
__device__ __forceinline__ void cpa16(uint32_t saddr, const void* g) {
    asm volatile("cp.async.ca.shared.global [%0], [%1], 16;" :: "r"(saddr), "l"(g));
}
#define CPA_COMMIT() asm volatile("cp.async.commit_group;" ::: "memory")
#define CPA_WAIT1()  asm volatile("cp.async.wait_group 1;" ::: "memory")
#define CPA_WAIT0()  asm volatile("cp.async.wait_group 0;" ::: "memory")

__device__ __forceinline__ void split_bf16(float v, __nv_bfloat16& h, __nv_bfloat16& l) {
    h = __float2bfloat16(v);
    l = __float2bfloat16(v - __bfloat162float(h));
}
// pack two floats -> bf16x2 hi word, and residual lo word
__device__ __forceinline__ uint32_t pack_split(float e0, float e1, uint32_t& lo) {
    __nv_bfloat162 h = __floats2bfloat162_rn(e0, e1);
    float2 f = __bfloat1622float2(h);
    __nv_bfloat162 l = __floats2bfloat162_rn(e0 - f.x, e1 - f.y);
    lo = *reinterpret_cast<uint32_t*>(&l);
    return *reinterpret_cast<uint32_t*>(&h);
}

// ================= smem layout for GEMM kernels =================
#define ROWB  144
#define SA_L  18432
#define SB_H  36864
#define SB_L  46080
#define STG   55296
#define SOFF  512
#define SMEM_GEMM (SOFF + 2 * STG)     // 111104

__device__ __forceinline__ void compute_chunk(uint32_t st, int wm, int wn, int lane,
                                              float acc[2][4][4])
{
    uint32_t a0r = st + (wm * 32 + (lane & 15)) * ROWB + ((lane >> 4) & 1) * 16;
    uint32_t b0r = st + SB_H + (wn * 32 + (lane & 7) + ((lane >> 4) & 1) * 8) * ROWB
                   + ((lane >> 3) & 1) * 16;
#pragma unroll
    for (int ks = 0; ks < 4; ks++) {
        uint32_t ah[2][4], al[2][4], bhA[4], bhB[4], blA[4], blB[4];
        ldsm4(ah[0], a0r + ks * 32);
        ldsm4(ah[1], a0r + 16 * ROWB + ks * 32);
        ldsm4(al[0], a0r + SA_L + ks * 32);
        ldsm4(al[1], a0r + SA_L + 16 * ROWB + ks * 32);
        ldsm4(bhA, b0r + ks * 32);
        ldsm4(bhB, b0r + 16 * ROWB + ks * 32);
        ldsm4(blA, b0r + (SB_L - SB_H) + ks * 32);
        ldsm4(blB, b0r + (SB_L - SB_H) + 16 * ROWB + ks * 32);
        uint32_t bh[4][2] = {{bhA[0], bhA[1]}, {bhA[2], bhA[3]}, {bhB[0], bhB[1]}, {bhB[2], bhB[3]}};
        uint32_t bl[4][2] = {{blA[0], blA[1]}, {blA[2], blA[3]}, {blB[0], blB[1]}, {blB[2], blB[3]}};
#pragma unroll
        for (int mf = 0; mf < 2; mf++)
#pragma unroll
            for (int nf = 0; nf < 4; nf++) {
                mma16816(acc[mf][nf], ah[mf], bh[nf][0], bh[nf][1]);
                mma16816(acc[mf][nf], al[mf], bh[nf][0], bh[nf][1]);
                mma16816(acc[mf][nf], ah[mf], bl[nf][0], bl[nf][1]);
            }
    }
}

// ================= split conversion kernel =================
__global__ void split_kernel(const float* __restrict__ in, __nv_bfloat16* __restrict__ hi,
                             __nv_bfloat16* __restrict__ lo, int n4)
{
    int i = blockIdx.x * blockDim.x + threadIdx.x;
    if (i >= n4) return;
    float4 v = reinterpret_cast<const float4*>(in)[i];
    __nv_bfloat162 h01 = __floats2bfloat162_rn(v.x, v.y);
    __nv_bfloat162 h23 = __floats2bfloat162_rn(v.z, v.w);
    float2 f01 = __bfloat1622float2(h01), f23 = __bfloat1622float2(h23);
    __nv_bfloat162 l01 = __floats2bfloat162_rn(v.x - f01.x, v.y - f01.y);
    __nv_bfloat162 l23 = __floats2bfloat162_rn(v.z - f23.x, v.w - f23.y);
    reinterpret_cast<__nv_bfloat162*>(hi)[2 * i]     = h01;
    reinterpret_cast<__nv_bfloat162*>(hi)[2 * i + 1] = h23;
    reinterpret_cast<__nv_bfloat162*>(lo)[2 * i]     = l01;
    reinterpret_cast<__nv_bfloat162*>(lo)[2 * i + 1] = l23;
}

// ================= QKV: M=128 N=64 K=192 per CTA =================
__global__ __launch_bounds__(256) void qkv_mma(const float* __restrict__ bias)
{
    extern __shared__ char sm[];
    uint32_t sb = smem_u32(sm);
    const int t = threadIdx.x, lane = t & 31, wid = t >> 5;
    const int wm = wid & 3, wn = wid >> 2;
    const int m0 = blockIdx.x * 128, j0 = blockIdx.y * 64;
    int* rowoff = (int*)sm;

    if (t < 128) {
        int m   = m0 + t;
        int bb  = m / NSEQ, n = m - bb * NSEQ;
        int r56 = n / 56, c56 = n - r56 * 56;
        int hb  = r56 / 7, hi_ = r56 - hb * 7;
        int wb  = c56 / 7, wi = c56 - wb * 7;
        rowoff[t] = ((bb * 64 + hb * 8 + wb) * 49 + hi_ * 7 + wi) * DIM;
    }
    __syncthreads();

    auto issue = [&](int i) {
        uint32_t st = sb + SOFF + (i & 1) * STG;
        int k0 = i * 64;
#pragma unroll
        for (int l = 0; l < 4; l++) {
            int idx = t + 256 * l;
            int row = idx >> 3, cg = idx & 7;
            uint32_t so = row * ROWB + cg * 16;
            int gi = rowoff[row] + k0 + cg * 8;
            cpa16(st + so, g_xh + gi);
            cpa16(st + SA_L + so, g_xl + gi);
        }
#pragma unroll
        for (int l = 0; l < 2; l++) {
            int idx = t + 256 * l;
            int row = idx >> 3, cg = idx & 7;
            uint32_t so = row * ROWB + cg * 16;
            int gi = (j0 + row) * DIM + k0 + cg * 8;
            cpa16(st + SB_H + so, g_wqh + gi);
            cpa16(st + SB_L + so, g_wql + gi);
        }
        CPA_COMMIT();
    };

    float acc[2][4][4] = {};
    issue(0);
    for (int i = 0; i < 3; i++) {
        if (i < 2) { issue(i + 1); CPA_WAIT1(); } else { CPA_WAIT0(); }
        __syncthreads();
        compute_chunk(sb + SOFF + (i & 1) * STG, wm, wn, lane, acc);
        __syncthreads();
    }

    const int seg = j0 / DIM;          // 0=q 1=k 2=v
    const int jb  = j0 - seg * DIM;
    __nv_bfloat16* H = (seg == 1) ? g_kTh : g_vTh;
    __nv_bfloat16* L = (seg == 1) ? g_kTl : g_vTl;
    const float scale = 0.17677669529663687f;
#pragma unroll
    for (int mf = 0; mf < 2; mf++)
#pragma unroll
        for (int rr = 0; rr < 2; rr++) {
            int ml = wm * 32 + mf * 16 + (lane >> 2) + rr * 8;
            int m  = m0 + ml;
            int b  = m / NSEQ, n = m - b * NSEQ;
#pragma unroll
            for (int nf = 0; nf < 4; nf++)
#pragma unroll
                for (int cp = 0; cp < 2; cp++) {
                    int c = wn * 32 + nf * 8 + (lane & 3) * 2 + cp;
                    float v = acc[mf][nf][rr * 2 + cp] + bias[j0 + c];
                    __nv_bfloat16 h_, l_;
                    if (seg == 0) {
                        int jj = jb + c;
                        split_bf16(v * scale, h_, l_);
                        int idx = ((b * HEADS + (jj >> 5)) * NSEQ + n) * HD + (jj & 31);
                        g_qh[idx] = h_;
                        g_ql[idx] = l_;
                    } else {
                        split_bf16(v, h_, l_);
                        int idx = (b * DIM + jb + c) * NSEQ + n;
                        H[idx] = h_;
                        L[idx] = l_;
                    }
                }
        }
}

// ================= low-rank: M=128(R) N=64 K=3136 =================
__global__ __launch_bounds__(256) void lowrank_mma(const float* __restrict__ Eb,
                                                   const float* __restrict__ Fb)
{
    extern __shared__ char sm[];
    uint32_t sb = smem_u32(sm);
    const int t = threadIdx.x, lane = t & 31, wid = t >> 5;
    const int wm = wid & 3, wn = wid >> 2;
    const int c0 = blockIdx.x * 64, b = blockIdx.y, which = blockIdx.z;

    const __nv_bfloat16* Ah = which ? g_Fh : g_Eh;
    const __nv_bfloat16* Al = which ? g_Fl : g_El;
    const __nv_bfloat16* Bh = which ? g_vTh : g_kTh;
    const __nv_bfloat16* Bl = which ? g_vTl : g_kTl;
    const float* bias = which ? Fb : Eb;

    auto issue = [&](int i) {
        uint32_t st = sb + SOFF + (i & 1) * STG;
        int k0 = i * 64;
#pragma unroll
        for (int l = 0; l < 4; l++) {
            int idx = t + 256 * l;
            int row = idx >> 3, cg = idx & 7;
            uint32_t so = row * ROWB + cg * 16;
            int gi = row * NSEQ + k0 + cg * 8;
            cpa16(st + so, Ah + gi);
            cpa16(st + SA_L + so, Al + gi);
        }
#pragma unroll
        for (int l = 0; l < 2; l++) {
            int idx = t + 256 * l;
            int row = idx >> 3, cg = idx & 7;
            uint32_t so = row * ROWB + cg * 16;
            int gi = (b * DIM + c0 + row) * NSEQ + k0 + cg * 8;
            cpa16(st + SB_H + so, Bh + gi);
            cpa16(st + SB_L + so, Bl + gi);
        }
        CPA_COMMIT();
    };

    float acc[2][4][4] = {};
    issue(0);
    for (int i = 0; i < 49; i++) {
        if (i < 48) { issue(i + 1); CPA_WAIT1(); } else { CPA_WAIT0(); }
        __syncthreads();
        compute_chunk(sb + SOFF + (i & 1) * STG, wm, wn, lane, acc);
        __syncthreads();
    }

#pragma unroll
    for (int mf = 0; mf < 2; mf++)
#pragma unroll
        for (int rr = 0; rr < 2; rr++) {
            int r = wm * 32 + mf * 16 + (lane >> 2) + rr * 8;
            float bv = bias[r];
#pragma unroll
            for (int nf = 0; nf < 4; nf++)
#pragma unroll
                for (int cp = 0; cp < 2; cp++) {
                    int c = wn * 32 + nf * 8 + (lane & 3) * 2 + cp;
                    float v = acc[mf][nf][rr * 2 + cp] + bv;
                    __nv_bfloat16 h_, l_;
                    split_bf16(v, h_, l_);
                    if (which == 0) {
                        int idx = (b * RLOW + r) * DIM + c0 + c;
                        g_klh[idx] = h_;
                        g_kll[idx] = l_;
                    } else {
                        int idx = (b * DIM + c0 + c) * RLOW + r;   // transposed
                        g_vlh[idx] = h_;
                        g_vll[idx] = l_;
                    }
                }
        }
}

// ================= attention: tensor-core flash-style =================
// per block: (b, head, 64 rows). 128 threads = 4 warps x 16 rows.
// smem: q hi/lo 64x32 (80B rows), klow hi/lo 128x32 (80B rows), vT hi/lo 32x128 (272B rows)
#define AQ_H 0
#define AQ_L 5120
#define AK_H 10240
#define AK_L 20480
#define AV_H 30720
#define AV_L 39424
#define ATT_SMEM 48128
__global__ __launch_bounds__(128) void attn_mma()
{
    extern __shared__ char sm[];
    uint32_t sb = smem_u32(sm);
    const int t = threadIdx.x, lane = t & 31, w = t >> 5;
    const int n0 = blockIdx.x * 64, hh = blockIdx.y, b = blockIdx.z;

    // loads
    {
        const __nv_bfloat16* qh = g_qh + ((b * HEADS + hh) * NSEQ + n0) * HD;
        const __nv_bfloat16* ql = g_ql + ((b * HEADS + hh) * NSEQ + n0) * HD;
#pragma unroll
        for (int l = 0; l < 2; l++) {
            int idx = t + 128 * l;              // 256 uint4
            int row = idx >> 2, cg = idx & 3;
            *(uint4*)(sm + AQ_H + row * 80 + cg * 16) = *(const uint4*)(qh + row * HD + cg * 8);
            *(uint4*)(sm + AQ_L + row * 80 + cg * 16) = *(const uint4*)(ql + row * HD + cg * 8);
        }
        const __nv_bfloat16* kh = g_klh + b * RLOW * DIM + hh * HD;
        const __nv_bfloat16* kl = g_kll + b * RLOW * DIM + hh * HD;
#pragma unroll
        for (int l = 0; l < 4; l++) {
            int idx = t + 128 * l;              // 512 uint4
            int row = idx >> 2, cg = idx & 3;
            *(uint4*)(sm + AK_H + row * 80 + cg * 16) = *(const uint4*)(kh + row * DIM + cg * 8);
            *(uint4*)(sm + AK_L + row * 80 + cg * 16) = *(const uint4*)(kl + row * DIM + cg * 8);
        }
        const __nv_bfloat16* vh = g_vlh + (b * DIM + hh * HD) * RLOW;
        const __nv_bfloat16* vl = g_vll + (b * DIM + hh * HD) * RLOW;
#pragma unroll
        for (int l = 0; l < 4; l++) {
            int idx = t + 128 * l;              // 512 uint4
            int row = idx >> 4, cg = idx & 15;
            *(uint4*)(sm + AV_H + row * 272 + cg * 16) = *(const uint4*)(vh + row * RLOW + cg * 8);
            *(uint4*)(sm + AV_L + row * 272 + cg * 16) = *(const uint4*)(vl + row * RLOW + cg * 8);
        }
    }
    __syncthreads();

    // phase 1: logits 16x128 per warp (K=32), 3-term split
    float acc[16][4] = {};
    {
        uint32_t qa = sb + AQ_H + (w * 16 + (lane & 15)) * 80 + ((lane >> 4) & 1) * 16;
        uint32_t ba = sb + AK_H + ((lane & 7) + ((lane >> 4) & 1) * 8) * 80 + ((lane >> 3) & 1) * 16;
#pragma unroll
        for (int ks = 0; ks < 2; ks++) {
            uint32_t aH[4], aL[4];
            ldsm4(aH, qa + ks * 32);
            ldsm4(aL, qa + (AQ_L - AQ_H) + ks * 32);
#pragma unroll
            for (int np = 0; np < 8; np++) {
                uint32_t bh[4], bl[4];
                ldsm4(bh, ba + np * 1280 + ks * 32);
                ldsm4(bl, ba + (AK_L - AK_H) + np * 1280 + ks * 32);
                mma16816(acc[2 * np], aH, bh[0], bh[1]);
                mma16816(acc[2 * np], aL, bh[0], bh[1]);
                mma16816(acc[2 * np], aH, bl[0], bl[1]);
                mma16816(acc[2 * np + 1], aH, bh[2], bh[3]);
                mma16816(acc[2 * np + 1], aL, bh[2], bh[3]);
                mma16816(acc[2 * np + 1], aH, bl[2], bl[3]);
            }
        }
    }

    // softmax in registers (rows gr = lane>>2 and gr+8)
    float m0 = -1e30f, m1 = -1e30f;
#pragma unroll
    for (int i = 0; i < 16; i++) {
        m0 = fmaxf(m0, fmaxf(acc[i][0], acc[i][1]));
        m1 = fmaxf(m1, fmaxf(acc[i][2], acc[i][3]));
    }
    m0 = fmaxf(m0, __shfl_xor_sync(0xffffffff, m0, 1));
    m0 = fmaxf(m0, __shfl_xor_sync(0xffffffff, m0, 2));
    m1 = fmaxf(m1, __shfl_xor_sync(0xffffffff, m1, 1));
    m1 = fmaxf(m1, __shfl_xor_sync(0xffffffff, m1, 2));
    float s0 = 0.f, s1 = 0.f;
#pragma unroll
    for (int i = 0; i < 16; i++) {
        acc[i][0] = __expf(acc[i][0] - m0); s0 += acc[i][0];
        acc[i][1] = __expf(acc[i][1] - m0); s0 += acc[i][1];
        acc[i][2] = __expf(acc[i][2] - m1); s1 += acc[i][2];
        acc[i][3] = __expf(acc[i][3] - m1); s1 += acc[i][3];
    }
    s0 += __shfl_xor_sync(0xffffffff, s0, 1);
    s0 += __shfl_xor_sync(0xffffffff, s0, 2);
    s1 += __shfl_xor_sync(0xffffffff, s1, 1);
    s1 += __shfl_xor_sync(0xffffffff, s1, 2);

    // phase 3: out = attn @ vlow (M=16, N=32, K=128); A fragments built from acc
    float oacc[4][4] = {};
    {
        uint32_t va = sb + AV_H + ((lane & 7) + ((lane >> 4) & 1) * 8) * 272 + ((lane >> 3) & 1) * 16;
#pragma unroll
        for (int kt = 0; kt < 8; kt++) {
            uint32_t ah[4], al[4];
            ah[0] = pack_split(acc[2 * kt][0],     acc[2 * kt][1],     al[0]);
            ah[1] = pack_split(acc[2 * kt][2],     acc[2 * kt][3],     al[1]);
            ah[2] = pack_split(acc[2 * kt + 1][0], acc[2 * kt + 1][1], al[2]);
            ah[3] = pack_split(acc[2 * kt + 1][2], acc[2 * kt + 1][3], al[3]);
#pragma unroll
            for (int np = 0; np < 2; np++) {
                uint32_t vh[4], vl[4];
                ldsm4(vh, va + np * 16 * 272 + kt * 32);
                ldsm4(vl, va + (AV_L - AV_H) + np * 16 * 272 + kt * 32);
                mma16816(oacc[2 * np], ah, vh[0], vh[1]);
                mma16816(oacc[2 * np], al, vh[0], vh[1]);
                mma16816(oacc[2 * np], ah, vl[0], vl[1]);
                mma16816(oacc[2 * np + 1], ah, vh[2], vh[3]);
                mma16816(oacc[2 * np + 1], al, vh[2], vh[3]);
                mma16816(oacc[2 * np + 1], ah, vl[2], vl[3]);
            }
        }
    }

    // epilogue: normalize + split-bf16 store to g_ah/g_al (b,n,c)
    {
        float inv0 = 1.0f / s0, inv1 = 1.0f / s1;
        int gr = lane >> 2;
        int row0 = n0 + w * 16 + gr, row1 = row0 + 8;
        int cbase = hh * HD + (lane & 3) * 2;
#pragma unroll
        for (int nf = 0; nf < 4; nf++) {
            int col = cbase + nf * 8;
            __nv_bfloat16 h_, l_;
            float v;
            v = oacc[nf][0] * inv0; split_bf16(v, h_, l_);
            g_ah[(b * NSEQ + row0) * DIM + col] = h_;     g_al[(b * NSEQ + row0) * DIM + col] = l_;
            v = oacc[nf][1] * inv0; split_bf16(v, h_, l_);
            g_ah[(b * NSEQ + row0) * DIM + col + 1] = h_; g_al[(b * NSEQ + row0) * DIM + col + 1] = l_;
            v = oacc[nf][2] * inv1; split_bf16(v, h_, l_);
            g_ah[(b * NSEQ + row1) * DIM + col] = h_;     g_al[(b * NSEQ + row1) * DIM + col] = l_;
            v = oacc[nf][3] * inv1; split_bf16(v, h_, l_);
            g_ah[(b * NSEQ + row1) * DIM + col + 1] = h_; g_al[(b * NSEQ + row1) * DIM + col + 1] = l_;
        }
    }
}

// ================= proj: M=128 N=64 K=192 per CTA =================
__global__ __launch_bounds__(256) void proj_mma(const float* __restrict__ bias,
                                                float* __restrict__ out)
{
    extern __shared__ char sm[];
    uint32_t sb = smem_u32(sm);
    const int t = threadIdx.x, lane = t & 31, wid = t >> 5;
    const int wm = wid & 3, wn = wid >> 2;
    const int m0 = blockIdx.x * 128, j0 = blockIdx.y * 64;

    auto issue = [&](int i) {
        uint32_t st = sb + SOFF + (i & 1) * STG;
        int k0 = i * 64;
#pragma unroll
        for (int l = 0; l < 4; l++) {
            int idx = t + 256 * l;
            int row = idx >> 3, cg = idx & 7;
            uint32_t so = row * ROWB + cg * 16;
            int gi = (m0 + row) * DIM + k0 + cg * 8;
            cpa16(st + so, g_ah + gi);
            cpa16(st + SA_L + so, g_al + gi);
        }
#pragma unroll
        for (int l = 0; l < 2; l++) {
            int idx = t + 256 * l;
            int row = idx >> 3, cg = idx & 7;
            uint32_t so = row * ROWB + cg * 16;
            int gi = (j0 + row) * DIM + k0 + cg * 8;
            cpa16(st + SB_H + so, g_wph + gi);
            cpa16(st + SB_L + so, g_wpl + gi);
        }
        CPA_COMMIT();
    };

    float acc[2][4][4] = {};
    issue(0);
    for (int i = 0; i < 3; i++) {
        if (i < 2) { issue(i + 1); CPA_WAIT1(); } else { CPA_WAIT0(); }
        __syncthreads();
        compute_chunk(sb + SOFF + (i & 1) * STG, wm, wn, lane, acc);
        __syncthreads();
    }

#pragma unroll
    for (int mf = 0; mf < 2; mf++)
#pragma unroll
        for (int rr = 0; rr < 2; rr++) {
            int m = m0 + wm * 32 + mf * 16 + (lane >> 2) + rr * 8;
#pragma unroll
            for (int nf = 0; nf < 4; nf++)
#pragma unroll
                for (int cp = 0; cp < 2; cp++) {
                    int c = wn * 32 + nf * 8 + (lane & 3) * 2 + cp;
                    out[m * DIM + j0 + c] = acc[mf][nf][rr * 2 + cp] + bias[j0 + c];
                }
        }
}

// ================= host =================
extern "C" void kernel_launch(void* const* d_in, const int* in_sizes, int n_in,
                              void* d_out, int out_size)
{
    const float* x      = (const float*)d_in[0];
    const float* qkv_b  = (const float*)d_in[2];
    const float* E_w    = (const float*)d_in[3];
    const float* E_b    = (const float*)d_in[4];
    const float* F_w    = (const float*)d_in[5];
    const float* F_b    = (const float*)d_in[6];
    const float* proj_w = (const float*)d_in[7];
    const float* proj_b = (const float*)d_in[8];
    const float* qkv_w  = (const float*)d_in[1];
    float* out = (float*)d_out;

    cudaFuncSetAttribute(qkv_mma, cudaFuncAttributeMaxDynamicSharedMemorySize, SMEM_GEMM);
    cudaFuncSetAttribute(lowrank_mma, cudaFuncAttributeMaxDynamicSharedMemorySize, SMEM_GEMM);
    cudaFuncSetAttribute(proj_mma, cudaFuncAttributeMaxDynamicSharedMemorySize, SMEM_GEMM);
    cudaFuncSetAttribute(attn_mma, cudaFuncAttributeMaxDynamicSharedMemorySize, ATT_SMEM);

    __nv_bfloat16 *xh, *xl, *wqh, *wql, *wph, *wpl, *Eh, *El, *Fh, *Fl;
    cudaGetSymbolAddress((void**)&xh, g_xh);   cudaGetSymbolAddress((void**)&xl, g_xl);
    cudaGetSymbolAddress((void**)&wqh, g_wqh); cudaGetSymbolAddress((void**)&wql, g_wql);
    cudaGetSymbolAddress((void**)&wph, g_wph); cudaGetSymbolAddress((void**)&wpl, g_wpl);
    cudaGetSymbolAddress((void**)&Eh, g_Eh);   cudaGetSymbolAddress((void**)&El, g_El);
    cudaGetSymbolAddress((void**)&Fh, g_Fh);   cudaGetSymbolAddress((void**)&Fl, g_Fl);

    int n4x = MTOT * DIM / 4;
    split_kernel<<<(n4x + 255) / 256, 256>>>(x, xh, xl, n4x);
    int n4q = 3 * DIM * DIM / 4;
    split_kernel<<<(n4q + 255) / 256, 256>>>(qkv_w, wqh, wql, n4q);
    int n4e = RLOW * NSEQ / 4;
    split_kernel<<<(n4e + 255) / 256, 256>>>(E_w, Eh, El, n4e);
    split_kernel<<<(n4e + 255) / 256, 256>>>(F_w, Fh, Fl, n4e);
    int n4p = DIM * DIM / 4;
    split_kernel<<<(n4p + 255) / 256, 256>>>(proj_w, wph, wpl, n4p);

    qkv_mma<<<dim3(MTOT / 128, 9), 256, SMEM_GEMM>>>(qkv_b);
    lowrank_mma<<<dim3(3, BATCH, 2), 256, SMEM_GEMM>>>(E_b, F_b);
    attn_mma<<<dim3(NSEQ / 64, HEADS, BATCH), 128, ATT_SMEM>>>();
    proj_mma<<<dim3(MTOT / 128, 3), 256, SMEM_GEMM>>>(proj_b, out);
}

// round 5
// speedup vs baseline: 3.6466x; 1.3181x over previous
#include <cuda_runtime.h>
#include <cuda_bf16.h>
#include <cstdint>
#include <math.h>

#define DIM   192
#define HEADS 6
#define HD    32
#define RLOW  128
#define NSEQ  3136
#define BATCH 32
#define MTOT  (BATCH * NSEQ)   // 100352

// ================= scratch (device globals) =================
__device__ __align__(256) __nv_bfloat16 g_xh[MTOT * DIM], g_xl[MTOT * DIM];
__device__ __align__(256) __nv_bfloat16 g_qh[MTOT * DIM], g_ql[MTOT * DIM];
__device__ __align__(256) __nv_bfloat16 g_kTh[MTOT * DIM], g_kTl[MTOT * DIM];
__device__ __align__(256) __nv_bfloat16 g_vTh[MTOT * DIM], g_vTl[MTOT * DIM];
__device__ __align__(256) __nv_bfloat16 g_ah[MTOT * DIM], g_al[MTOT * DIM];
__device__ __align__(256) __nv_bfloat16 g_klh[BATCH * RLOW * DIM], g_kll[BATCH * RLOW * DIM];
__device__ __align__(256) __nv_bfloat16 g_vlh[BATCH * DIM * RLOW], g_vll[BATCH * DIM * RLOW];
__device__ __align__(256) __nv_bfloat16 g_wqh[3 * DIM * DIM], g_wql[3 * DIM * DIM];
__device__ __align__(256) __nv_bfloat16 g_wph[DIM * DIM], g_wpl[DIM * DIM];
__device__ __align__(256) __nv_bfloat16 g_Eh[RLOW * NSEQ], g_El[RLOW * NSEQ];
__device__ __align__(256) __nv_bfloat16 g_Fh[RLOW * NSEQ], g_Fl[RLOW * NSEQ];

// ================= helpers =================
__device__ __forceinline__ uint32_t smem_u32(const void* p) {
    uint32_t a;
    asm("{ .reg .u64 t; cvta.to.shared.u64 t, %1; cvt.u32.u64 %0, t; }" : "=r"(a) : "l"(p));
    return a;
}
__device__ __forceinline__ void ldsm4(uint32_t r[4], uint32_t a) {
    asm volatile("ldmatrix.sync.aligned.m8n8.x4.shared.b16 {%0,%1,%2,%3}, [%4];"
                 : "=r"(r[0]), "=r"(r[1]), "=r"(r[2]), "=r"(r[3]) : "r"(a));
}
__device__ __forceinline__ void mma16816(float* c, const uint32_t a[4], uint32_t b0, uint32_t b1) {
    asm volatile("mma.sync.aligned.m16n8k16.row.col.f32.bf16.bf16.f32 "
                 "{%0,%1,%2,%3},{%4,%5,%6,%7},{%8,%9},{%0,%1,%2,%3};"
                 : "+f"(c[0]), "+f"(c[1]), "+f"(c[2]), "+f"(c[3])
                 : "r"(a[0]), "r"(a[1]), "r"(a[2]), "r"(a[3]), "r"(b0), "r"(b1));
}
__device__ __forceinline__ void cpa16(uint32_t saddr, const void* g) {
    asm volatile("cp.async.ca.shared.global [%0], [%1], 16;" :: "r"(saddr), "l"(g));
}
#define CPA_COMMIT() asm volatile("cp.async.commit_group;" ::: "memory")
#define CPA_WAIT1()  asm volatile("cp.async.wait_group 1;" ::: "memory")
#define CPA_WAIT0()  asm volatile("cp.async.wait_group 0;" ::: "memory")

__device__ __forceinline__ void split_bf16(float v, __nv_bfloat16& h, __nv_bfloat16& l) {
    h = __float2bfloat16(v);
    l = __float2bfloat16(v - __bfloat162float(h));
}
__device__ __forceinline__ uint32_t pack_split(float e0, float e1, uint32_t& lo) {
    __nv_bfloat162 h = __floats2bfloat162_rn(e0, e1);
    float2 f = __bfloat1622float2(h);
    __nv_bfloat162 l = __floats2bfloat162_rn(e0 - f.x, e1 - f.y);
    lo = *reinterpret_cast<uint32_t*>(&l);
    return *reinterpret_cast<uint32_t*>(&h);
}

// ================= GEMM smem layout: K-chunk 32, 2 stages =================
// stage: A_hi 128x32 (80B rows) | A_lo | B_hi 64x32 | B_lo = 30720 B
#define ROWB   80
#define S_AL   10240
#define S_BH   20480
#define S_BL   25600
#define STG    30720
#define SOFF   512
#define SMEM_GEMM (SOFF + 2 * STG)   // 61952

__device__ __forceinline__ void compute_chunk(uint32_t st, int wm, int wn, int lane,
                                              float acc[2][4][4])
{
    uint32_t a0r = st + (wm * 32 + (lane & 15)) * ROWB + ((lane >> 4) & 1) * 16;
    uint32_t b0r = st + S_BH + (wn * 32 + (lane & 7) + ((lane >> 4) & 1) * 8) * ROWB
                   + ((lane >> 3) & 1) * 16;
#pragma unroll
    for (int ks = 0; ks < 2; ks++) {
        uint32_t ah[2][4], al[2][4], bhA[4], bhB[4], blA[4], blB[4];
        ldsm4(ah[0], a0r + ks * 32);
        ldsm4(ah[1], a0r + 16 * ROWB + ks * 32);
        ldsm4(al[0], a0r + S_AL + ks * 32);
        ldsm4(al[1], a0r + S_AL + 16 * ROWB + ks * 32);
        ldsm4(bhA, b0r + ks * 32);
        ldsm4(bhB, b0r + 16 * ROWB + ks * 32);
        ldsm4(blA, b0r + (S_BL - S_BH) + ks * 32);
        ldsm4(blB, b0r + (S_BL - S_BH) + 16 * ROWB + ks * 32);
        uint32_t bh[4][2] = {{bhA[0], bhA[1]}, {bhA[2], bhA[3]}, {bhB[0], bhB[1]}, {bhB[2], bhB[3]}};
        uint32_t bl[4][2] = {{blA[0], blA[1]}, {blA[2], blA[3]}, {blB[0], blB[1]}, {blB[2], blB[3]}};
#pragma unroll
        for (int mf = 0; mf < 2; mf++)
#pragma unroll
            for (int nf = 0; nf < 4; nf++) {
                mma16816(acc[mf][nf], ah[mf], bh[nf][0], bh[nf][1]);
                mma16816(acc[mf][nf], al[mf], bh[nf][0], bh[nf][1]);
                mma16816(acc[mf][nf], ah[mf], bl[nf][0], bl[nf][1]);
            }
    }
}

// ================= split conversion =================
__global__ void split_kernel(const float* __restrict__ in, __nv_bfloat16* __restrict__ hi,
                             __nv_bfloat16* __restrict__ lo, int n4)
{
    int i = blockIdx.x * blockDim.x + threadIdx.x;
    if (i >= n4) return;
    float4 v = reinterpret_cast<const float4*>(in)[i];
    __nv_bfloat162 h01 = __floats2bfloat162_rn(v.x, v.y);
    __nv_bfloat162 h23 = __floats2bfloat162_rn(v.z, v.w);
    float2 f01 = __bfloat1622float2(h01), f23 = __bfloat1622float2(h23);
    __nv_bfloat162 l01 = __floats2bfloat162_rn(v.x - f01.x, v.y - f01.y);
    __nv_bfloat162 l23 = __floats2bfloat162_rn(v.z - f23.x, v.w - f23.y);
    reinterpret_cast<__nv_bfloat162*>(hi)[2 * i]     = h01;
    reinterpret_cast<__nv_bfloat162*>(hi)[2 * i + 1] = h23;
    reinterpret_cast<__nv_bfloat162*>(lo)[2 * i]     = l01;
    reinterpret_cast<__nv_bfloat162*>(lo)[2 * i + 1] = l23;
}

// ================= QKV: M=128 N=64 K=192 (6 chunks) =================
__global__ __launch_bounds__(256, 2) void qkv_mma(const float* __restrict__ bias)
{
    extern __shared__ char sm[];
    uint32_t sb = smem_u32(sm);
    const int t = threadIdx.x, lane = t & 31, wid = t >> 5;
    const int wm = wid & 3, wn = wid >> 2;
    const int m0 = blockIdx.x * 128, j0 = blockIdx.y * 64;
    int* rowoff = (int*)sm;

    if (t < 128) {
        int m   = m0 + t;
        int bb  = m / NSEQ, n = m - bb * NSEQ;
        int r56 = n / 56, c56 = n - r56 * 56;
        int hb  = r56 / 7, hi_ = r56 - hb * 7;
        int wb  = c56 / 7, wi = c56 - wb * 7;
        rowoff[t] = ((bb * 64 + hb * 8 + wb) * 49 + hi_ * 7 + wi) * DIM;
    }
    __syncthreads();

    auto issue = [&](int i) {
        uint32_t st = sb + SOFF + (i & 1) * STG;
        int k0 = i * 32;
#pragma unroll
        for (int l = 0; l < 2; l++) {
            int idx = t + 256 * l;             // 512: A 128 rows x 4 groups
            int row = idx >> 2, cg = idx & 3;
            uint32_t so = row * ROWB + cg * 16;
            int gi = rowoff[row] + k0 + cg * 8;
            cpa16(st + so, g_xh + gi);
            cpa16(st + S_AL + so, g_xl + gi);
        }
        {
            int row = t >> 2, cg = t & 3;      // 256: B 64 rows x 4 groups
            uint32_t so = row * ROWB + cg * 16;
            int gi = (j0 + row) * DIM + t >= 0 ? (j0 + row) * DIM + k0 + cg * 8 : 0;
            cpa16(st + S_BH + so, g_wqh + gi);
            cpa16(st + S_BL + so, g_wql + gi);
        }
        CPA_COMMIT();
    };

    float acc[2][4][4] = {};
    issue(0);
    for (int i = 0; i < 6; i++) {
        if (i < 5) { issue(i + 1); CPA_WAIT1(); } else { CPA_WAIT0(); }
        __syncthreads();
        compute_chunk(sb + SOFF + (i & 1) * STG, wm, wn, lane, acc);
        __syncthreads();
    }

    // ---- staged epilogue ----
    const int seg = j0 / DIM;          // 0=q 1=k 2=v
    const int jb  = j0 - seg * DIM;
    uint32_t eb = sb + SOFF;
    const float scale = 0.17677669529663687f;

    if (seg == 0) {
        // stage [n][c], stride 144; hi at eb, lo at eb+18432
#pragma unroll
        for (int mf = 0; mf < 2; mf++)
#pragma unroll
            for (int rr = 0; rr < 2; rr++) {
                int ml = wm * 32 + mf * 16 + (lane >> 2) + rr * 8;
#pragma unroll
                for (int nf = 0; nf < 4; nf++)
#pragma unroll
                    for (int cp = 0; cp < 2; cp++) {
                        int c = wn * 32 + nf * 8 + (lane & 3) * 2 + cp;
                        float v = (acc[mf][nf][rr * 2 + cp] + bias[j0 + c]) * scale;
                        __nv_bfloat16 h_, l_;
                        split_bf16(v, h_, l_);
                        *(__nv_bfloat16*)(sm + (eb - sb) + ml * 144 + c * 2) = h_;
                        *(__nv_bfloat16*)(sm + (eb - sb) + 18432 + ml * 144 + c * 2) = l_;
                    }
            }
        __syncthreads();
        const int h0 = jb >> 5;
#pragma unroll
        for (int l = 0; l < 2; l++) {
            int idx = t + 256 * l;             // 512 tasks of 64B
            int hl = idx >> 8, rem = idx & 255;
            int row = rem >> 1, q = rem & 1;
            int m = m0 + row, b = m / NSEQ, n = m - b * NSEQ;
            const uint4* src = (const uint4*)(sm + SOFF + hl * 18432 + row * 144 + q * 64);
            __nv_bfloat16* dst = (hl ? g_ql : g_qh) + ((b * HEADS + h0 + q) * NSEQ + n) * HD;
#pragma unroll
            for (int u = 0; u < 4; u++) ((uint4*)dst)[u] = src[u];
        }
    } else {
        // stage [c][n], stride 272; hi at eb, lo at eb+17408
#pragma unroll
        for (int mf = 0; mf < 2; mf++)
#pragma unroll
            for (int rr = 0; rr < 2; rr++) {
                int ml = wm * 32 + mf * 16 + (lane >> 2) + rr * 8;
#pragma unroll
                for (int nf = 0; nf < 4; nf++)
#pragma unroll
                    for (int cp = 0; cp < 2; cp++) {
                        int c = wn * 32 + nf * 8 + (lane & 3) * 2 + cp;
                        float v = acc[mf][nf][rr * 2 + cp] + bias[j0 + c];
                        __nv_bfloat16 h_, l_;
                        split_bf16(v, h_, l_);
                        *(__nv_bfloat16*)(sm + (eb - sb) + c * 272 + ml * 2) = h_;
                        *(__nv_bfloat16*)(sm + (eb - sb) + 17408 + c * 272 + ml * 2) = l_;
                    }
            }
        __syncthreads();
        __nv_bfloat16* H = (seg == 1) ? g_kTh : g_vTh;
        __nv_bfloat16* L = (seg == 1) ? g_kTl : g_vTl;
#pragma unroll
        for (int l = 0; l < 8; l++) {
            int idx = t + 256 * l;             // 2048 uint4
            int row = idx >> 4, g = idx & 15;  // row: hl*64 + c
            int hl = row >> 6, c = row & 63;
            int m = m0 + g * 8, b = m / NSEQ, n = m - b * NSEQ;
            uint4 v = *(const uint4*)(sm + SOFF + hl * 17408 + c * 272 + g * 16);
            *(uint4*)((hl ? L : H) + (b * DIM + jb + c) * NSEQ + n) = v;
        }
    }
}

// ================= low-rank: M=128 N=64 K=3136 (98 chunks) =================
__global__ __launch_bounds__(256, 2) void lowrank_mma(const float* __restrict__ Eb,
                                                      const float* __restrict__ Fb)
{
    extern __shared__ char sm[];
    uint32_t sb = smem_u32(sm);
    const int t = threadIdx.x, lane = t & 31, wid = t >> 5;
    const int wm = wid & 3, wn = wid >> 2;
    const int c0 = blockIdx.x * 64, b = blockIdx.y, which = blockIdx.z;

    const __nv_bfloat16* Ah = which ? g_Fh : g_Eh;
    const __nv_bfloat16* Al = which ? g_Fl : g_El;
    const __nv_bfloat16* Bh = which ? g_vTh : g_kTh;
    const __nv_bfloat16* Bl = which ? g_vTl : g_kTl;
    const float* bias = which ? Fb : Eb;

    auto issue = [&](int i) {
        uint32_t st = sb + SOFF + (i & 1) * STG;
        int k0 = i * 32;
#pragma unroll
        for (int l = 0; l < 2; l++) {
            int idx = t + 256 * l;
            int row = idx >> 2, cg = idx & 3;
            uint32_t so = row * ROWB + cg * 16;
            int gi = row * NSEQ + k0 + cg * 8;
            cpa16(st + so, Ah + gi);
            cpa16(st + S_AL + so, Al + gi);
        }
        {
            int row = t >> 2, cg = t & 3;
            uint32_t so = row * ROWB + cg * 16;
            int gi = (b * DIM + c0 + row) * NSEQ + k0 + cg * 8;
            cpa16(st + S_BH + so, Bh + gi);
            cpa16(st + S_BL + so, Bl + gi);
        }
        CPA_COMMIT();
    };

    float acc[2][4][4] = {};
    issue(0);
    for (int i = 0; i < 98; i++) {
        if (i < 97) { issue(i + 1); CPA_WAIT1(); } else { CPA_WAIT0(); }
        __syncthreads();
        compute_chunk(sb + SOFF + (i & 1) * STG, wm, wn, lane, acc);
        __syncthreads();
    }

    if (which == 0) {
        // klow (b,R,c): stage [r][c], stride 144
#pragma unroll
        for (int mf = 0; mf < 2; mf++)
#pragma unroll
            for (int rr = 0; rr < 2; rr++) {
                int r = wm * 32 + mf * 16 + (lane >> 2) + rr * 8;
                float bv = bias[r];
#pragma unroll
                for (int nf = 0; nf < 4; nf++)
#pragma unroll
                    for (int cp = 0; cp < 2; cp++) {
                        int c = wn * 32 + nf * 8 + (lane & 3) * 2 + cp;
                        float v = acc[mf][nf][rr * 2 + cp] + bv;
                        __nv_bfloat16 h_, l_;
                        split_bf16(v, h_, l_);
                        *(__nv_bfloat16*)(sm + SOFF + r * 144 + c * 2) = h_;
                        *(__nv_bfloat16*)(sm + SOFF + 18432 + r * 144 + c * 2) = l_;
                    }
            }
        __syncthreads();
#pragma unroll
        for (int l = 0; l < 2; l++) {
            int idx = t + 256 * l;             // 512 tasks of 64B (128 r x 2 hl x 2 halves)
            int hl = idx >> 8, rem = idx & 255;
            int r = rem >> 1, half = rem & 1;
            const uint4* src = (const uint4*)(sm + SOFF + hl * 18432 + r * 144 + half * 64);
            __nv_bfloat16* dst = (hl ? g_kll : g_klh) + (b * RLOW + r) * DIM + c0 + half * 32;
#pragma unroll
            for (int u = 0; u < 4; u++) ((uint4*)dst)[u] = src[u];
        }
    } else {
        // vlow^T (b,c,R): stage [c][r], stride 272
#pragma unroll
        for (int mf = 0; mf < 2; mf++)
#pragma unroll
            for (int rr = 0; rr < 2; rr++) {
                int r = wm * 32 + mf * 16 + (lane >> 2) + rr * 8;
                float bv = bias[r];
#pragma unroll
                for (int nf = 0; nf < 4; nf++)
#pragma unroll
                    for (int cp = 0; cp < 2; cp++) {
                        int c = wn * 32 + nf * 8 + (lane & 3) * 2 + cp;
                        float v = acc[mf][nf][rr * 2 + cp] + bv;
                        __nv_bfloat16 h_, l_;
                        split_bf16(v, h_, l_);
                        *(__nv_bfloat16*)(sm + SOFF + c * 272 + r * 2) = h_;
                        *(__nv_bfloat16*)(sm + SOFF + 17408 + c * 272 + r * 2) = l_;
                    }
            }
        __syncthreads();
#pragma unroll
        for (int l = 0; l < 8; l++) {
            int idx = t + 256 * l;             // 2048 uint4
            int row = idx >> 4, g = idx & 15;
            int hl = row >> 6, c = row & 63;
            uint4 v = *(const uint4*)(sm + SOFF + hl * 17408 + c * 272 + g * 16);
            *(uint4*)((hl ? g_vll : g_vlh) + (b * DIM + c0 + c) * RLOW + g * 8) = v;
        }
    }
}

// ================= attention (unchanged from R4) =================
#define AQ_H 0
#define AQ_L 5120
#define AK_H 10240
#define AK_L 20480
#define AV_H 30720
#define AV_L 39424
#define ATT_SMEM 48128
__global__ __launch_bounds__(128) void attn_mma()
{
    extern __shared__ char sm[];
    uint32_t sb = smem_u32(sm);
    const int t = threadIdx.x, lane = t & 31, w = t >> 5;
    const int n0 = blockIdx.x * 64, hh = blockIdx.y, b = blockIdx.z;

    {
        const __nv_bfloat16* qh = g_qh + ((b * HEADS + hh) * NSEQ + n0) * HD;
        const __nv_bfloat16* ql = g_ql + ((b * HEADS + hh) * NSEQ + n0) * HD;
#pragma unroll
        for (int l = 0; l < 2; l++) {
            int idx = t + 128 * l;
            int row = idx >> 2, cg = idx & 3;
            *(uint4*)(sm + AQ_H + row * 80 + cg * 16) = *(const uint4*)(qh + row * HD + cg * 8);
            *(uint4*)(sm + AQ_L + row * 80 + cg * 16) = *(const uint4*)(ql + row * HD + cg * 8);
        }
        const __nv_bfloat16* kh = g_klh + b * RLOW * DIM + hh * HD;
        const __nv_bfloat16* kl = g_kll + b * RLOW * DIM + hh * HD;
#pragma unroll
        for (int l = 0; l < 4; l++) {
            int idx = t + 128 * l;
            int row = idx >> 2, cg = idx & 3;
            *(uint4*)(sm + AK_H + row * 80 + cg * 16) = *(const uint4*)(kh + row * DIM + cg * 8);
            *(uint4*)(sm + AK_L + row * 80 + cg * 16) = *(const uint4*)(kl + row * DIM + cg * 8);
        }
        const __nv_bfloat16* vh = g_vlh + (b * DIM + hh * HD) * RLOW;
        const __nv_bfloat16* vl = g_vll + (b * DIM + hh * HD) * RLOW;
#pragma unroll
        for (int l = 0; l < 4; l++) {
            int idx = t + 128 * l;
            int row = idx >> 4, cg = idx & 15;
            *(uint4*)(sm + AV_H + row * 272 + cg * 16) = *(const uint4*)(vh + row * RLOW + cg * 8);
            *(uint4*)(sm + AV_L + row * 272 + cg * 16) = *(const uint4*)(vl + row * RLOW + cg * 8);
        }
    }
    __syncthreads();

    float acc[16][4] = {};
    {
        uint32_t qa = sb + AQ_H + (w * 16 + (lane & 15)) * 80 + ((lane >> 4) & 1) * 16;
        uint32_t ba = sb + AK_H + ((lane & 7) + ((lane >> 4) & 1) * 8) * 80 + ((lane >> 3) & 1) * 16;
#pragma unroll
        for (int ks = 0; ks < 2; ks++) {
            uint32_t aH[4], aL[4];
            ldsm4(aH, qa + ks * 32);
            ldsm4(aL, qa + (AQ_L - AQ_H) + ks * 32);
#pragma unroll
            for (int np = 0; np < 8; np++) {
                uint32_t bh[4], bl[4];
                ldsm4(bh, ba + np * 1280 + ks * 32);
                ldsm4(bl, ba + (AK_L - AK_H) + np * 1280 + ks * 32);
                mma16816(acc[2 * np], aH, bh[0], bh[1]);
                mma16816(acc[2 * np], aL, bh[0], bh[1]);
                mma16816(acc[2 * np], aH, bl[0], bl[1]);
                mma16816(acc[2 * np + 1], aH, bh[2], bh[3]);
                mma16816(acc[2 * np + 1], aL, bh[2], bh[3]);
                mma16816(acc[2 * np + 1], aH, bl[2], bl[3]);
            }
        }
    }

    float m0 = -1e30f, m1 = -1e30f;
#pragma unroll
    for (int i = 0; i < 16; i++) {
        m0 = fmaxf(m0, fmaxf(acc[i][0], acc[i][1]));
        m1 = fmaxf(m1, fmaxf(acc[i][2], acc[i][3]));
    }
    m0 = fmaxf(m0, __shfl_xor_sync(0xffffffff, m0, 1));
    m0 = fmaxf(m0, __shfl_xor_sync(0xffffffff, m0, 2));
    m1 = fmaxf(m1, __shfl_xor_sync(0xffffffff, m1, 1));
    m1 = fmaxf(m1, __shfl_xor_sync(0xffffffff, m1, 2));
    float s0 = 0.f, s1 = 0.f;
#pragma unroll
    for (int i = 0; i < 16; i++) {
        acc[i][0] = __expf(acc[i][0] - m0); s0 += acc[i][0];
        acc[i][1] = __expf(acc[i][1] - m0); s0 += acc[i][1];
        acc[i][2] = __expf(acc[i][2] - m1); s1 += acc[i][2];
        acc[i][3] = __expf(acc[i][3] - m1); s1 += acc[i][3];
    }
    s0 += __shfl_xor_sync(0xffffffff, s0, 1);
    s0 += __shfl_xor_sync(0xffffffff, s0, 2);
    s1 += __shfl_xor_sync(0xffffffff, s1, 1);
    s1 += __shfl_xor_sync(0xffffffff, s1, 2);

    float oacc[4][4] = {};
    {
        uint32_t va = sb + AV_H + ((lane & 7) + ((lane >> 4) & 1) * 8) * 272 + ((lane >> 3) & 1) * 16;
#pragma unroll
        for (int kt = 0; kt < 8; kt++) {
            uint32_t ah[4], al[4];
            ah[0] = pack_split(acc[2 * kt][0],     acc[2 * kt][1],     al[0]);
            ah[1] = pack_split(acc[2 * kt][2],     acc[2 * kt][3],     al[1]);
            ah[2] = pack_split(acc[2 * kt + 1][0], acc[2 * kt + 1][1], al[2]);
            ah[3] = pack_split(acc[2 * kt + 1][2], acc[2 * kt + 1][3], al[3]);
#pragma unroll
            for (int np = 0; np < 2; np++) {
                uint32_t vh[4], vl[4];
                ldsm4(vh, va + np * 16 * 272 + kt * 32);
                ldsm4(vl, va + (AV_L - AV_H) + np * 16 * 272 + kt * 32);
                mma16816(oacc[2 * np], ah, vh[0], vh[1]);
                mma16816(oacc[2 * np], al, vh[0], vh[1]);
                mma16816(oacc[2 * np], ah, vl[0], vl[1]);
                mma16816(oacc[2 * np + 1], ah, vh[2], vh[3]);
                mma16816(oacc[2 * np + 1], al, vh[2], vh[3]);
                mma16816(oacc[2 * np + 1], ah, vl[2], vl[3]);
            }
        }
    }

    {
        float inv0 = 1.0f / s0, inv1 = 1.0f / s1;
        int gr = lane >> 2;
        int row0 = n0 + w * 16 + gr, row1 = row0 + 8;
        int cbase = hh * HD + (lane & 3) * 2;
#pragma unroll
        for (int nf = 0; nf < 4; nf++) {
            int col = cbase + nf * 8;
            __nv_bfloat16 h_, l_;
            float v;
            v = oacc[nf][0] * inv0; split_bf16(v, h_, l_);
            g_ah[(b * NSEQ + row0) * DIM + col] = h_;     g_al[(b * NSEQ + row0) * DIM + col] = l_;
            v = oacc[nf][1] * inv0; split_bf16(v, h_, l_);
            g_ah[(b * NSEQ + row0) * DIM + col + 1] = h_; g_al[(b * NSEQ + row0) * DIM + col + 1] = l_;
            v = oacc[nf][2] * inv1; split_bf16(v, h_, l_);
            g_ah[(b * NSEQ + row1) * DIM + col] = h_;     g_al[(b * NSEQ + row1) * DIM + col] = l_;
            v = oacc[nf][3] * inv1; split_bf16(v, h_, l_);
            g_ah[(b * NSEQ + row1) * DIM + col + 1] = h_; g_al[(b * NSEQ + row1) * DIM + col + 1] = l_;
        }
    }
}

// ================= proj: M=128 N=64 K=192 (6 chunks) =================
__global__ __launch_bounds__(256, 2) void proj_mma(const float* __restrict__ bias,
                                                   float* __restrict__ out)
{
    extern __shared__ char sm[];
    uint32_t sb = smem_u32(sm);
    const int t = threadIdx.x, lane = t & 31, wid = t >> 5;
    const int wm = wid & 3, wn = wid >> 2;
    const int m0 = blockIdx.x * 128, j0 = blockIdx.y * 64;

    auto issue = [&](int i) {
        uint32_t st = sb + SOFF + (i & 1) * STG;
        int k0 = i * 32;
#pragma unroll
        for (int l = 0; l < 2; l++) {
            int idx = t + 256 * l;
            int row = idx >> 2, cg = idx & 3;
            uint32_t so = row * ROWB + cg * 16;
            int gi = (m0 + row) * DIM + k0 + cg * 8;
            cpa16(st + so, g_ah + gi);
            cpa16(st + S_AL + so, g_al + gi);
        }
        {
            int row = t >> 2, cg = t & 3;
            uint32_t so = row * ROWB + cg * 16;
            int gi = (j0 + row) * DIM + k0 + cg * 8;
            cpa16(st + S_BH + so, g_wph + gi);
            cpa16(st + S_BL + so, g_wpl + gi);
        }
        CPA_COMMIT();
    };

    float acc[2][4][4] = {};
    issue(0);
    for (int i = 0; i < 6; i++) {
        if (i < 5) { issue(i + 1); CPA_WAIT1(); } else { CPA_WAIT0(); }
        __syncthreads();
        compute_chunk(sb + SOFF + (i & 1) * STG, wm, wn, lane, acc);
        __syncthreads();
    }

    // stage fp32 [m][c], stride 272B
#pragma unroll
    for (int mf = 0; mf < 2; mf++)
#pragma unroll
        for (int rr = 0; rr < 2; rr++) {
            int ml = wm * 32 + mf * 16 + (lane >> 2) + rr * 8;
#pragma unroll
            for (int nf = 0; nf < 4; nf++)
#pragma unroll
                for (int cp = 0; cp < 2; cp++) {
                    int c = wn * 32 + nf * 8 + (lane & 3) * 2 + cp;
                    *(float*)(sm + SOFF + ml * 272 + c * 4) =
                        acc[mf][nf][rr * 2 + cp] + bias[j0 + c];
                }
        }
    __syncthreads();
#pragma unroll
    for (int l = 0; l < 8; l++) {
        int idx = t + 256 * l;             // 2048 uint4: 128 rows x 16
        int row = idx >> 4, g = idx & 15;
        uint4 v = *(const uint4*)(sm + SOFF + row * 272 + g * 16);
        *(uint4*)(out + (m0 + row) * DIM + j0 + g * 4) = v;
    }
}

// ================= host =================
extern "C" void kernel_launch(void* const* d_in, const int* in_sizes, int n_in,
                              void* d_out, int out_size)
{
    const float* x      = (const float*)d_in[0];
    const float* qkv_w  = (const float*)d_in[1];
    const float* qkv_b  = (const float*)d_in[2];
    const float* E_w    = (const float*)d_in[3];
    const float* E_b    = (const float*)d_in[4];
    const float* F_w    = (const float*)d_in[5];
    const float* F_b    = (const float*)d_in[6];
    const float* proj_w = (const float*)d_in[7];
    const float* proj_b = (const float*)d_in[8];
    float* out = (float*)d_out;

    cudaFuncSetAttribute(qkv_mma, cudaFuncAttributeMaxDynamicSharedMemorySize, SMEM_GEMM);
    cudaFuncSetAttribute(lowrank_mma, cudaFuncAttributeMaxDynamicSharedMemorySize, SMEM_GEMM);
    cudaFuncSetAttribute(proj_mma, cudaFuncAttributeMaxDynamicSharedMemorySize, SMEM_GEMM);
    cudaFuncSetAttribute(attn_mma, cudaFuncAttributeMaxDynamicSharedMemorySize, ATT_SMEM);

    __nv_bfloat16 *xh, *xl, *wqh, *wql, *wph, *wpl, *Eh, *El, *Fh, *Fl;
    cudaGetSymbolAddress((void**)&xh, g_xh);   cudaGetSymbolAddress((void**)&xl, g_xl);
    cudaGetSymbolAddress((void**)&wqh, g_wqh); cudaGetSymbolAddress((void**)&wql, g_wql);
    cudaGetSymbolAddress((void**)&wph, g_wph); cudaGetSymbolAddress((void**)&wpl, g_wpl);
    cudaGetSymbolAddress((void**)&Eh, g_Eh);   cudaGetSymbolAddress((void**)&El, g_El);
    cudaGetSymbolAddress((void**)&Fh, g_Fh);   cudaGetSymbolAddress((void**)&Fl, g_Fl);

    int n4x = MTOT * DIM / 4;
    split_kernel<<<(n4x + 255) / 256, 256>>>(x, xh, xl, n4x);
    int n4q = 3 * DIM * DIM / 4;
    split_kernel<<<(n4q + 255) / 256, 256>>>(qkv_w, wqh, wql, n4q);
    int n4e = RLOW * NSEQ / 4;
    split_kernel<<<(n4e + 255) / 256, 256>>>(E_w, Eh, El, n4e);
    split_kernel<<<(n4e + 255) / 256, 256>>>(F_w, Fh, Fl, n4e);
    int n4p = DIM * DIM / 4;
    split_kernel<<<(n4p + 255) / 256, 256>>>(proj_w, wph, wpl, n4p);

    qkv_mma<<<dim3(MTOT / 128, 9), 256, SMEM_GEMM>>>(qkv_b);
    lowrank_mma<<<dim3(3, BATCH, 2), 256, SMEM_GEMM>>>(E_b, F_b);
    attn_mma<<<dim3(NSEQ / 64, HEADS, BATCH), 128, ATT_SMEM>>>();
    proj_mma<<<dim3(MTOT / 128, 3), 256, SMEM_GEMM>>>(proj_b, out);
}